// round 2
// baseline (speedup 1.0000x reference)
#include <cuda_runtime.h>
#include <math.h>

#define ADIM 6
#define ZDIM 32
#define HDIM 512
#define EDIM 1024
#define BATCH 256
#define TSTEPS 64

// output layout: h_seq[B,T,H] | z_seq | pm | ps | qm | qs (each [B,T,Z])
#define OFF_Z  (BATCH*TSTEPS*HDIM)
#define ZBLK   (BATCH*TSTEPS*ZDIM)
#define OFF_PM (OFF_Z + ZBLK)
#define OFF_PS (OFF_PM + ZBLK)
#define OFF_QM (OFF_PS + ZBLK)
#define OFF_QS (OFF_QM + ZBLK)

// scratch (device globals; no dynamic allocation allowed)
__device__ __align__(128) float g_preAZ[BATCH*TSTEPS*HDIM]; // b_az + a@W_az_a, [b][t][h]
__device__ __align__(128) float g_preHA[BATCH*TSTEPS*HDIM]; // b_ha + a@W_ha_a
__device__ __align__(128) float g_preHE[BATCH*TSTEPS*HDIM]; // b_he + e@W_he_e
__device__ __align__(128) float g_G[BATCH*3072];            // [gi(1536)|gh(1536)]
__device__ __align__(128) float g_h[BATCH*HDIM];
__device__ __align__(128) float g_x[BATCH*HDIM];
__device__ __align__(128) float g_z[BATCH*ZDIM];
__device__ __align__(128) float g_hahe[BATCH*1024];         // [ha(512)|he(512)]
__device__ __align__(128) float g_WazzT[ZDIM*HDIM];         // W_az[:, :32] transposed [k][h]
__device__ __align__(128) float g_Wha[HDIM*HDIM];           // W_ha[:, :512] packed

__device__ __forceinline__ float sigmoidf_(float x) { return 1.f / (1.f + expf(-x)); }
__device__ __forceinline__ float softplusf_(float x) {
    return fmaxf(x, 0.f) + log1pf(expf(-fabsf(x)));
}

// ---------------------------------------------------------------------------
__global__ void k_init(const float* __restrict__ prev_z, const float* __restrict__ prev_h) {
    int idx = blockIdx.x * 256 + threadIdx.x;
    if (idx < BATCH*HDIM) g_h[idx] = prev_h[idx];
    if (idx < BATCH*ZDIM) g_z[idx] = prev_z[idx];
}

// pack W_ha[:, :512] (row stride 518, unaligned) and W_az[:, :32] transposed
__global__ void k_pack(const float* __restrict__ W_az, const float* __restrict__ W_ha) {
    int n = blockIdx.x;             // 0..511
    int tid = threadIdx.x;          // 256
    g_Wha[n*HDIM + tid]       = W_ha[n*(HDIM+ADIM) + tid];
    g_Wha[n*HDIM + tid + 256] = W_ha[n*(HDIM+ADIM) + tid + 256];
    if (tid < ZDIM) g_WazzT[tid*HDIM + n] = W_az[n*(ZDIM+ADIM) + tid];
}

// preAZ, preHA (action projections + biases). grid=64 (t), 256 thr
__global__ __launch_bounds__(256) void k_pre_act(
    const float* __restrict__ actions,
    const float* __restrict__ W_az, const float* __restrict__ b_az,
    const float* __restrict__ W_ha, const float* __restrict__ b_ha)
{
    __shared__ float waz[HDIM*ADIM];
    __shared__ float wha[HDIM*ADIM];
    __shared__ float baz[HDIM];
    __shared__ float bha[HDIM];
    __shared__ float act[BATCH*ADIM];
    const int t = blockIdx.x;
    const int tid = threadIdx.x;
    for (int e = tid; e < HDIM*ADIM; e += 256) {
        int h = e / ADIM, j = e - h*ADIM;
        waz[e] = W_az[h*(ZDIM+ADIM) + ZDIM + j];
        wha[e] = W_ha[h*(HDIM+ADIM) + HDIM + j];
    }
    for (int e = tid; e < HDIM; e += 256) { baz[e] = b_az[e]; bha[e] = b_ha[e]; }
    for (int e = tid; e < BATCH*ADIM; e += 256) {
        int b = e / ADIM, j = e - b*ADIM;
        act[e] = actions[(b*TSTEPS + t)*ADIM + j];
    }
    __syncthreads();
    for (int e = tid; e < BATCH*HDIM; e += 256) {
        int b = e >> 9, h = e & 511;
        float pa = baz[h], ph = bha[h];
        #pragma unroll
        for (int j = 0; j < ADIM; j++) {
            float a = act[b*ADIM + j];
            pa += a * waz[h*ADIM + j];
            ph += a * wha[h*ADIM + j];
        }
        int o = (b*TSTEPS + t)*HDIM + h;
        g_preAZ[o] = pa;
        g_preHA[o] = ph;
    }
}

// preHE = b_he + e @ W_he[:,512:].T   M=16384 (r=b*64+t), N=512, K=1024
// 64x64 tile, BK=16, 256 threads, 4x4 microtile. grid (256, 8)
__global__ __launch_bounds__(256) void k_pre_he(
    const float* __restrict__ emb, const float* __restrict__ W_he,
    const float* __restrict__ b_he)
{
    const int m0 = blockIdx.x * 64;
    const int n0 = blockIdx.y * 64;
    const int tid = threadIdx.x;
    const int tx = tid & 15, ty = tid >> 4;
    const int lr = tid >> 2, lk = (tid & 3) << 2;
    __shared__ float As[16][65];
    __shared__ float Bs[16][65];
    float acc[4][4] = {};
    const float* Ap = emb + (size_t)(m0 + lr)*EDIM + lk;
    const float* Bp = W_he + (size_t)(n0 + lr)*1536 + 512 + lk;
    for (int k0 = 0; k0 < EDIM; k0 += 16) {
        float4 av = *(const float4*)(Ap + k0);
        float4 bv = *(const float4*)(Bp + k0);
        __syncthreads();
        As[lk][lr]=av.x; As[lk+1][lr]=av.y; As[lk+2][lr]=av.z; As[lk+3][lr]=av.w;
        Bs[lk][lr]=bv.x; Bs[lk+1][lr]=bv.y; Bs[lk+2][lr]=bv.z; Bs[lk+3][lr]=bv.w;
        __syncthreads();
        #pragma unroll
        for (int kk = 0; kk < 16; kk++) {
            float a0=As[kk][ty*4], a1=As[kk][ty*4+1], a2=As[kk][ty*4+2], a3=As[kk][ty*4+3];
            float b0=Bs[kk][tx*4], b1=Bs[kk][tx*4+1], b2=Bs[kk][tx*4+2], b3=Bs[kk][tx*4+3];
            acc[0][0]+=a0*b0; acc[0][1]+=a0*b1; acc[0][2]+=a0*b2; acc[0][3]+=a0*b3;
            acc[1][0]+=a1*b0; acc[1][1]+=a1*b1; acc[1][2]+=a1*b2; acc[1][3]+=a1*b3;
            acc[2][0]+=a2*b0; acc[2][1]+=a2*b1; acc[2][2]+=a2*b2; acc[2][3]+=a2*b3;
            acc[3][0]+=a3*b0; acc[3][1]+=a3*b1; acc[3][2]+=a3*b2; acc[3][3]+=a3*b3;
        }
    }
    #pragma unroll
    for (int i = 0; i < 4; i++)
        #pragma unroll
        for (int j = 0; j < 4; j++) {
            int r = m0 + ty*4 + i, c = n0 + tx*4 + j;
            g_preHE[r*HDIM + c] = acc[i][j] + b_he[c];
        }
}

// x = relu(zmask @ WzzT + preAZ[t]). grid=BATCH, 512 thr
__global__ void k_x(const float* __restrict__ dones, int t) {
    const int b = blockIdx.x, h = threadIdx.x;
    __shared__ float sz[ZDIM];
    if (h < ZDIM) sz[h] = g_z[b*ZDIM + h] * (1.f - dones[b*TSTEPS + t]);
    __syncthreads();
    float acc = g_preAZ[(b*TSTEPS + t)*HDIM + h];
    #pragma unroll
    for (int k = 0; k < ZDIM; k++) acc += sz[k] * g_WazzT[k*HDIM + h];
    g_x[b*HDIM + h] = fmaxf(acc, 0.f);
}

// G = [gi | gh]: dual-A GEMM [256, 3072], K=512. grid (4, 48)
__global__ __launch_bounds__(256) void k_gates(
    const float* __restrict__ W_ih, const float* __restrict__ W_hh,
    const float* __restrict__ b_ih, const float* __restrict__ b_hh)
{
    const int m0 = blockIdx.x * 64;
    const int n0 = blockIdx.y * 64;
    const bool isI = (n0 < 1536);
    const float* A = isI ? g_x : g_h;
    const float* B = isI ? (W_ih + (size_t)n0*HDIM) : (W_hh + (size_t)(n0-1536)*HDIM);
    const float* bias = isI ? (b_ih + n0) : (b_hh + (n0-1536));
    const int tid = threadIdx.x;
    const int tx = tid & 15, ty = tid >> 4;
    const int lr = tid >> 2, lk = (tid & 3) << 2;
    __shared__ float As[16][65];
    __shared__ float Bs[16][65];
    float acc[4][4] = {};
    const float* Ap = A + (m0 + lr)*HDIM + lk;
    const float* Bp = B + lr*HDIM + lk;
    for (int k0 = 0; k0 < HDIM; k0 += 16) {
        float4 av = *(const float4*)(Ap + k0);
        float4 bv = *(const float4*)(Bp + k0);
        __syncthreads();
        As[lk][lr]=av.x; As[lk+1][lr]=av.y; As[lk+2][lr]=av.z; As[lk+3][lr]=av.w;
        Bs[lk][lr]=bv.x; Bs[lk+1][lr]=bv.y; Bs[lk+2][lr]=bv.z; Bs[lk+3][lr]=bv.w;
        __syncthreads();
        #pragma unroll
        for (int kk = 0; kk < 16; kk++) {
            float a0=As[kk][ty*4], a1=As[kk][ty*4+1], a2=As[kk][ty*4+2], a3=As[kk][ty*4+3];
            float b0=Bs[kk][tx*4], b1=Bs[kk][tx*4+1], b2=Bs[kk][tx*4+2], b3=Bs[kk][tx*4+3];
            acc[0][0]+=a0*b0; acc[0][1]+=a0*b1; acc[0][2]+=a0*b2; acc[0][3]+=a0*b3;
            acc[1][0]+=a1*b0; acc[1][1]+=a1*b1; acc[1][2]+=a1*b2; acc[1][3]+=a1*b3;
            acc[2][0]+=a2*b0; acc[2][1]+=a2*b1; acc[2][2]+=a2*b2; acc[2][3]+=a2*b3;
            acc[3][0]+=a3*b0; acc[3][1]+=a3*b1; acc[3][2]+=a3*b2; acc[3][3]+=a3*b3;
        }
    }
    #pragma unroll
    for (int i = 0; i < 4; i++)
        #pragma unroll
        for (int j = 0; j < 4; j++)
            g_G[(m0 + ty*4 + i)*3072 + n0 + tx*4 + j] = acc[i][j] + bias[tx*4 + j];
}

// GRU gate fuse. grid 512, 256 thr
__global__ void k_gru(float* __restrict__ out, int t) {
    int idx = blockIdx.x * 256 + threadIdx.x;  // 131072
    int b = idx >> 9, j = idx & 511;
    const float* Gb = g_G + b*3072;
    float r = sigmoidf_(Gb[j] + Gb[1536 + j]);
    float u = sigmoidf_(Gb[512 + j] + Gb[2048 + j]);
    float n = tanhf(Gb[1024 + j] + r * Gb[2560 + j]);
    float hp = g_h[idx];
    float h = (1.f - u)*n + u*hp;
    g_h[idx] = h;
    out[b*TSTEPS*HDIM + t*HDIM + j] = h;
}

// hahe = relu(h @ [Wha_h | Whe_h] + [preHA|preHE]). [256,1024], K=512. grid (4,16)
__global__ __launch_bounds__(256) void k_hahe(const float* __restrict__ W_he, int t) {
    const int m0 = blockIdx.x * 64;
    const int n0 = blockIdx.y * 64;
    const bool isHA = (n0 < 512);
    const float* B = isHA ? (g_Wha + (size_t)n0*HDIM) : (W_he + (size_t)(n0-512)*1536);
    const int ldb = isHA ? HDIM : 1536;
    const float* pre = isHA ? g_preHA : g_preHE;
    const int pc0 = isHA ? n0 : (n0 - 512);
    const int tid = threadIdx.x;
    const int tx = tid & 15, ty = tid >> 4;
    const int lr = tid >> 2, lk = (tid & 3) << 2;
    __shared__ float As[16][65];
    __shared__ float Bs[16][65];
    float acc[4][4] = {};
    const float* Ap = g_h + (m0 + lr)*HDIM + lk;
    const float* Bp = B + lr*ldb + lk;
    for (int k0 = 0; k0 < HDIM; k0 += 16) {
        float4 av = *(const float4*)(Ap + k0);
        float4 bv = *(const float4*)(Bp + k0);
        __syncthreads();
        As[lk][lr]=av.x; As[lk+1][lr]=av.y; As[lk+2][lr]=av.z; As[lk+3][lr]=av.w;
        Bs[lk][lr]=bv.x; Bs[lk+1][lr]=bv.y; Bs[lk+2][lr]=bv.z; Bs[lk+3][lr]=bv.w;
        __syncthreads();
        #pragma unroll
        for (int kk = 0; kk < 16; kk++) {
            float a0=As[kk][ty*4], a1=As[kk][ty*4+1], a2=As[kk][ty*4+2], a3=As[kk][ty*4+3];
            float b0=Bs[kk][tx*4], b1=Bs[kk][tx*4+1], b2=Bs[kk][tx*4+2], b3=Bs[kk][tx*4+3];
            acc[0][0]+=a0*b0; acc[0][1]+=a0*b1; acc[0][2]+=a0*b2; acc[0][3]+=a0*b3;
            acc[1][0]+=a1*b0; acc[1][1]+=a1*b1; acc[1][2]+=a1*b2; acc[1][3]+=a1*b3;
            acc[2][0]+=a2*b0; acc[2][1]+=a2*b1; acc[2][2]+=a2*b2; acc[2][3]+=a2*b3;
            acc[3][0]+=a3*b0; acc[3][1]+=a3*b1; acc[3][2]+=a3*b2; acc[3][3]+=a3*b3;
        }
    }
    #pragma unroll
    for (int i = 0; i < 4; i++)
        #pragma unroll
        for (int j = 0; j < 4; j++) {
            int r = ty*4 + i, c = tx*4 + j, b = m0 + r;
            float v = acc[i][j] + pre[(b*TSTEPS + t)*HDIM + pc0 + c];
            g_hahe[b*1024 + n0 + c] = fmaxf(v, 0.f);
        }
}

// heads: prior=ha@W_prior.T, post=he@W_post.T; softplus; rsample. grid 4, 256 thr
__global__ __launch_bounds__(256) void k_heads(
    const float* __restrict__ W_prior, const float* __restrict__ b_prior,
    const float* __restrict__ W_post, const float* __restrict__ b_post,
    const float* __restrict__ post_noise, float* __restrict__ out, int t)
{
    const int m0 = blockIdx.x * 64;
    const int tid = threadIdx.x;
    const int tx = tid & 15, ty = tid >> 4;   // cols tx*8..+7, rows ty*4..+3
    const int lr = tid >> 2, lk = (tid & 3) << 2;
    const int wr = tid >> 1, wk = (tid & 1) << 3;
    __shared__ float Aha[16][65];
    __shared__ float Ahe[16][65];
    __shared__ float Ws[16][130];
    __shared__ float Spost[64][65];
    float acc[4][8] = {};
    const float* ApH = g_hahe + (m0 + lr)*1024 + lk;
    const float* ApE = ApH + 512;
    const float* Wrow = (wr < 64) ? (W_prior + wr*HDIM + wk) : (W_post + (wr-64)*HDIM + wk);
    for (int k0 = 0; k0 < HDIM; k0 += 16) {
        float4 a = *(const float4*)(ApH + k0);
        float4 e = *(const float4*)(ApE + k0);
        float4 w0 = *(const float4*)(Wrow + k0);
        float4 w1 = *(const float4*)(Wrow + k0 + 4);
        __syncthreads();
        Aha[lk][lr]=a.x; Aha[lk+1][lr]=a.y; Aha[lk+2][lr]=a.z; Aha[lk+3][lr]=a.w;
        Ahe[lk][lr]=e.x; Ahe[lk+1][lr]=e.y; Ahe[lk+2][lr]=e.z; Ahe[lk+3][lr]=e.w;
        Ws[wk][wr]=w0.x; Ws[wk+1][wr]=w0.y; Ws[wk+2][wr]=w0.z; Ws[wk+3][wr]=w0.w;
        Ws[wk+4][wr]=w1.x; Ws[wk+5][wr]=w1.y; Ws[wk+6][wr]=w1.z; Ws[wk+7][wr]=w1.w;
        __syncthreads();
        const float (*Asel)[65] = (tx < 8) ? Aha : Ahe;
        #pragma unroll
        for (int kk = 0; kk < 16; kk++) {
            float av[4], bv[8];
            #pragma unroll
            for (int i = 0; i < 4; i++) av[i] = Asel[kk][ty*4 + i];
            #pragma unroll
            for (int j = 0; j < 8; j++) bv[j] = Ws[kk][tx*8 + j];
            #pragma unroll
            for (int i = 0; i < 4; i++)
                #pragma unroll
                for (int j = 0; j < 8; j++) acc[i][j] += av[i]*bv[j];
        }
    }
    #pragma unroll
    for (int i = 0; i < 4; i++)
        #pragma unroll
        for (int j = 0; j < 8; j++) {
            int c = tx*8 + j, r = ty*4 + i, b = m0 + r;
            if (c < 64) {
                float v = acc[i][j] + b_prior[c];
                if (c < 32) out[OFF_PM + b*TSTEPS*ZDIM + t*ZDIM + c] = v;
                else        out[OFF_PS + b*TSTEPS*ZDIM + t*ZDIM + (c-32)] = softplusf_(v);
            } else {
                Spost[r][c - 64] = acc[i][j] + b_post[c - 64];
            }
        }
    __syncthreads();
    for (int s = tid; s < 64*ZDIM; s += 256) {
        int r = s >> 5, j = s & 31, b = m0 + r;
        float qm = Spost[r][j];
        float qs = softplusf_(Spost[r][32 + j]);
        float eps = post_noise[(b*TSTEPS + t)*ZDIM + j];
        float z = qm + qs*eps;
        int o = b*TSTEPS*ZDIM + t*ZDIM + j;
        out[OFF_QM + o] = qm;
        out[OFF_QS + o] = qs;
        out[OFF_Z  + o] = z;
        g_z[b*ZDIM + j] = z;
    }
}

extern "C" void kernel_launch(void* const* d_in, const int* in_sizes, int n_in,
                              void* d_out, int out_size) {
    const float* prev_z   = (const float*)d_in[0];
    const float* prev_h   = (const float*)d_in[1];
    const float* actions  = (const float*)d_in[2];
    const float* emb      = (const float*)d_in[3];
    const float* dones    = (const float*)d_in[4];
    // d_in[5] = prior_noise (unused by reference)
    const float* post_noise = (const float*)d_in[6];
    const float* W_az = (const float*)d_in[7];
    const float* b_az = (const float*)d_in[8];
    const float* W_ih = (const float*)d_in[9];
    const float* W_hh = (const float*)d_in[10];
    const float* b_ih = (const float*)d_in[11];
    const float* b_hh = (const float*)d_in[12];
    const float* W_ha = (const float*)d_in[13];
    const float* b_ha = (const float*)d_in[14];
    const float* W_prior = (const float*)d_in[15];
    const float* b_prior = (const float*)d_in[16];
    const float* W_he = (const float*)d_in[17];
    const float* b_he = (const float*)d_in[18];
    const float* W_post = (const float*)d_in[19];
    const float* b_post = (const float*)d_in[20];
    float* out = (float*)d_out;

    k_init<<<512, 256>>>(prev_z, prev_h);
    k_pack<<<512, 256>>>(W_az, W_ha);
    k_pre_act<<<64, 256>>>(actions, W_az, b_az, W_ha, b_ha);
    k_pre_he<<<dim3(256, 8), 256>>>(emb, W_he, b_he);

    for (int t = 0; t < TSTEPS; t++) {
        k_x<<<BATCH, 512>>>(dones, t);
        k_gates<<<dim3(4, 48), 256>>>(W_ih, W_hh, b_ih, b_hh);
        k_gru<<<512, 256>>>(out, t);
        k_hahe<<<dim3(4, 16), 256>>>(W_he, t);
        k_heads<<<4, 256>>>(W_prior, b_prior, W_post, b_post, post_noise, out, t);
    }
}